// round 15
// baseline (speedup 1.0000x reference)
#include <cuda_runtime.h>
#include <cuda_fp16.h>
#include <math.h>

#define H   96
#define W   96
#define HW  9216
#define HP  98
#define HPWP 9604
#define CIN 512
#define C1  256
#define C2  64
#define BATCH 2
#define NS  9
#define COFF 28
#define KTOT (C1*NS)
#define EPSV 1e-5f
#define F2TOT (BATCH * C1 * HPWP)

#define WPIT 40
#define BPIT128 136

// conv1 dynamic smem layout (3-stage)
#define C1_A_STRIDE (128 * WPIT)
#define C1_B_STRIDE (32 * BPIT128)
#define C1SM_AH 0
#define C1SM_AL (C1SM_AH + 3 * C1_A_STRIDE * 2)
#define C1SM_BH (C1SM_AL + 3 * C1_A_STRIDE * 2)
#define C1SM_BL (C1SM_BH + 3 * C1_B_STRIDE * 2)
#define C1_SMEM (C1SM_BL + 3 * C1_B_STRIDE * 2)

// ---------------- scratch ----------------
__device__ float g_f1[BATCH * C1 * HW];
__device__ uint2 g_f2q[F2TOT + 2];                  // fp16 quad plane (v, v+1, v+HP, v+HP+1)
__device__ unsigned short g_f2h[F2TOT];             // single fp16 plane, offconv B
__device__ unsigned short g_xh[BATCH * CIN * HW];
__device__ unsigned short g_xl[BATCH * CIN * HW];
__device__ float g_off[BATCH * COFF * HW];
__device__ float g_s1[CIN * 2];
__device__ float g_s2[C1 * 2];
__device__ float g_biasC[32];
__device__ unsigned short g_w1h[C1 * CIN];
__device__ unsigned short g_w1l[C1 * CIN];
__device__ unsigned short g_w6h[32 * KTOT];
__device__ unsigned short g_w6l[32 * KTOT];
__device__ unsigned short g_w7h[C2 * KTOT];
__device__ unsigned short g_w7l[C2 * KTOT];

// ---------------- helpers ----------------
__device__ __forceinline__ void splith(float v, unsigned short* hp, unsigned short* lp) {
    __half h = __float2half(v);
    float hf = __half2float(h);
    __half l = __float2half(v - hf);
    *hp = __half_as_ushort(h);
    *lp = __half_as_ushort(l);
}

__device__ __forceinline__ unsigned short h16(float v) {
    return __half_as_ushort(__float2half(v));
}

__device__ __forceinline__ unsigned smaddr(const void* p) {
    return (unsigned)__cvta_generic_to_shared(p);
}

__device__ __forceinline__ void cpa16(void* dst, const void* src) {
    asm volatile("cp.async.cg.shared.global [%0], [%1], 16;"
                 :: "r"(smaddr(dst)), "l"(src));
}
__device__ __forceinline__ void cpa_commit() {
    asm volatile("cp.async.commit_group;");
}
__device__ __forceinline__ void cpa_wait0() {
    asm volatile("cp.async.wait_group 0;");
}
__device__ __forceinline__ void cpa_wait1() {
    asm volatile("cp.async.wait_group 1;");
}

__device__ __forceinline__ void ldsm4(unsigned* r, unsigned a) {
    asm volatile("ldmatrix.sync.aligned.m8n8.x4.shared.b16 {%0,%1,%2,%3}, [%4];"
                 : "=r"(r[0]), "=r"(r[1]), "=r"(r[2]), "=r"(r[3])
                 : "r"(a));
}

__device__ __forceinline__ void ldsm4t(unsigned* r, unsigned a) {
    asm volatile("ldmatrix.sync.aligned.m8n8.x4.trans.shared.b16 {%0,%1,%2,%3}, [%4];"
                 : "=r"(r[0]), "=r"(r[1]), "=r"(r[2]), "=r"(r[3])
                 : "r"(a));
}

__device__ __forceinline__ void mma16816(float* c, const unsigned* a, const unsigned* b) {
    asm volatile("mma.sync.aligned.m16n8k16.row.col.f32.f16.f16.f32 "
                 "{%0,%1,%2,%3}, {%4,%5,%6,%7}, {%8,%9}, {%0,%1,%2,%3};"
                 : "+f"(c[0]), "+f"(c[1]), "+f"(c[2]), "+f"(c[3])
                 : "r"(a[0]), "r"(a[1]), "r"(a[2]), "r"(a[3]), "r"(b[0]), "r"(b[1]));
}

__device__ __forceinline__ void load_a_frag(unsigned* a, const unsigned short* base,
                                            int pitch, int row0, int kb, int lane) {
    const unsigned short* p = base + (row0 + (lane & 15)) * pitch + kb + ((lane >> 4) * 8);
    ldsm4(a, smaddr(p));
}

__device__ __forceinline__ void load_b_frag(unsigned b0[2], unsigned b1[2],
                                            const unsigned short* base,
                                            int pitch, int kb, int n0, int lane) {
    unsigned tmp[4];
    const unsigned short* p = base + (kb + (lane & 15)) * pitch + n0 + ((lane >> 4) * 8);
    ldsm4t(tmp, smaddr(p));
    b0[0] = tmp[0];
    b0[1] = tmp[1];
    b1[0] = tmp[2];
    b1[1] = tmp[3];
}

// ---------------- weight prep (+ zero stat accumulators each replay) --------
__global__ void prep_kernel(const float* __restrict__ w1,
                            const float* __restrict__ pw, const float* __restrict__ pb,
                            const float* __restrict__ mw, const float* __restrict__ mb,
                            const float* __restrict__ dw, const float* __restrict__ db,
                            const float* __restrict__ w7) {
    int i = blockIdx.x * blockDim.x + threadIdx.x;
    if (i < CIN * 2) {
        g_s1[i] = 0.f;
    }
    if (i < C1 * 2) {
        g_s2[i] = 0.f;
    }
    if (i < C1 * CIN) {
        splith(w1[i], &g_w1h[i], &g_w1l[i]);
    }
    if (i < 32 * KTOT) {
        int co = i / KTOT;
        int k = i % KTOT;
        int r = k / C1;
        int ci = k % C1;
        float v = 0.f;
        if (co < 18) {
            v = pw[(co * C1 + ci) * NS + r];
        } else if (co < 27) {
            v = mw[((co - 18) * C1 + ci) * NS + r];
        } else if (co == 27) {
            v = dw[ci * NS + r];
        }
        splith(v, &g_w6h[i], &g_w6l[i]);
    }
    if (i < C2 * KTOT) {
        int o = i / KTOT;
        int k = i % KTOT;
        int n = k / C1;
        int ci = k % C1;
        splith(w7[(o * C1 + ci) * NS + n], &g_w7h[i], &g_w7l[i]);
    }
    if (i < 32) {
        float v = 0.f;
        if (i < 18) {
            v = pb[i];
        } else if (i < 27) {
            v = mb[i - 18];
        } else if (i == 27) {
            v = db[0];
        }
        g_biasC[i] = v;
    }
}

// ---------------- BN partial sums (atomic, 4-way) ----------------
__device__ __forceinline__ void bn_partial_reduce(float s, float s2, float* sh,
                                                  float* dst, int c) {
    sh[threadIdx.x] = s;
    sh[256 + threadIdx.x] = s2;
    __syncthreads();
    for (int st = 128; st > 0; st >>= 1) {
        if (threadIdx.x < st) {
            sh[threadIdx.x] += sh[threadIdx.x + st];
            sh[256 + threadIdx.x] += sh[256 + threadIdx.x + st];
        }
        __syncthreads();
    }
    if (threadIdx.x == 0) {
        atomicAdd(&dst[2 * c], sh[0]);
        atomicAdd(&dst[2 * c + 1], sh[256]);
    }
}

__global__ void bn1_partial_kernel(const float* __restrict__ x) {
    __shared__ float sh[512];
    int c = blockIdx.x;
    int part = blockIdx.y;
    int bb = part >> 1;
    int hf = part & 1;
    const float4* pl = (const float4*)(x + ((size_t)(bb * CIN + c)) * HW) + hf * (HW / 8);
    float s = 0.f;
    float s2 = 0.f;
    for (int q = threadIdx.x; q < HW / 8; q += 256) {
        float4 v = pl[q];
        s += v.x + v.y + v.z + v.w;
        s2 += v.x * v.x + v.y * v.y + v.z * v.z + v.w * v.w;
    }
    bn_partial_reduce(s, s2, sh, g_s1, c);
}

__global__ void bn2_partial_kernel() {
    __shared__ float sh[512];
    int c = blockIdx.x;
    int part = blockIdx.y;
    int bb = part >> 1;
    int hf = part & 1;
    const float4* pl = (const float4*)(g_f1 + ((size_t)(bb * C1 + c)) * HW) + hf * (HW / 8);
    float s = 0.f;
    float s2 = 0.f;
    for (int q = threadIdx.x; q < HW / 8; q += 256) {
        float4 v = pl[q];
        s += v.x + v.y + v.z + v.w;
        s2 += v.x * v.x + v.y * v.y + v.z * v.z + v.w * v.w;
    }
    bn_partial_reduce(s, s2, sh, g_s2, c);
}

// ---------------- xcvt: BN1 finalize + ReLU + fp16 split ----------------
__global__ void xcvt_kernel(const float* __restrict__ x,
                            const float* __restrict__ gamma,
                            const float* __restrict__ beta) {
    int i4 = blockIdx.x * blockDim.x + threadIdx.x;
    if (i4 >= BATCH * CIN * HW / 4) {
        return;
    }
    int c = (i4 * 4 / HW) % CIN;
    const float inv = 1.f / (float)(BATCH * HW);
    float mean = g_s1[2 * c] * inv;
    float var = g_s1[2 * c + 1] * inv - mean * mean;
    float a = gamma[c] * rsqrtf(var + EPSV);
    float b = beta[c] - mean * a;
    float4 v = ((const float4*)x)[i4];
    ushort4 oh;
    ushort4 ol;
    splith(fmaxf(fmaf(a, v.x, b), 0.f), &oh.x, &ol.x);
    splith(fmaxf(fmaf(a, v.y, b), 0.f), &oh.y, &ol.y);
    splith(fmaxf(fmaf(a, v.z, b), 0.f), &oh.z, &ol.z);
    splith(fmaxf(fmaf(a, v.w, b), 0.f), &oh.w, &ol.w);
    ((ushort4*)g_xh)[i4] = oh;
    ((ushort4*)g_xl)[i4] = ol;
}

// ---------------- conv1: 128x128, 3-stage, 1 sync/chunk (proven) -----------
__global__ __launch_bounds__(256) void conv1_kernel(const float* __restrict__ bias) {
    extern __shared__ char smc[];
    unsigned short* AhS = (unsigned short*)(smc + C1SM_AH);
    unsigned short* AlS = (unsigned short*)(smc + C1SM_AL);
    unsigned short* BhS = (unsigned short*)(smc + C1SM_BH);
    unsigned short* BlS = (unsigned short*)(smc + C1SM_BL);
    const int bz = blockIdx.z;
    const int p0 = blockIdx.x * 128;
    const int cob = blockIdx.y * 128;
    const int t = threadIdx.x;
    const int lane = t & 31;
    const int wid = t >> 5;
    const int m0 = (wid >> 1) * 32;
    const int n0 = (wid & 1) * 64;
    const unsigned short* __restrict__ xh = g_xh + (size_t)bz * CIN * HW;
    const unsigned short* __restrict__ xl = g_xl + (size_t)bz * CIN * HW;

    const int ar0 = t >> 2;
    const int ac = (t & 3) * 8;
    const int br0 = t >> 4;
    const int bc = (t & 15) * 8;

    float acc[2][8][4];
    #pragma unroll
    for (int mt = 0; mt < 2; mt++) {
        #pragma unroll
        for (int nf = 0; nf < 8; nf++) {
            #pragma unroll
            for (int q = 0; q < 4; q++) {
                acc[mt][nf][q] = 0.f;
            }
        }
    }

    #pragma unroll
    for (int pc = 0; pc < 2; pc++) {
        const int k0 = pc * 32;
        unsigned short* ahd = AhS + pc * C1_A_STRIDE;
        unsigned short* ald = AlS + pc * C1_A_STRIDE;
        unsigned short* bhd = BhS + pc * C1_B_STRIDE;
        unsigned short* bld = BlS + pc * C1_B_STRIDE;
        #pragma unroll
        for (int i = 0; i < 2; i++) {
            int r = ar0 + i * 64;
            cpa16(ahd + r * WPIT + ac, g_w1h + (cob + r) * CIN + k0 + ac);
            cpa16(ald + r * WPIT + ac, g_w1l + (cob + r) * CIN + k0 + ac);
        }
        #pragma unroll
        for (int i = 0; i < 2; i++) {
            int r = br0 + i * 16;
            cpa16(bhd + r * BPIT128 + bc, xh + (k0 + r) * HW + p0 + bc);
            cpa16(bld + r * BPIT128 + bc, xl + (k0 + r) * HW + p0 + bc);
        }
        cpa_commit();
    }

    int s = 0;
    int sp = 2;
    for (int cc = 0; cc < 16; cc++) {
        cpa_wait1();
        __syncthreads();
        if (cc < 14) {
            const int k0 = (cc + 2) * 32;
            unsigned short* ahd = AhS + sp * C1_A_STRIDE;
            unsigned short* ald = AlS + sp * C1_A_STRIDE;
            unsigned short* bhd = BhS + sp * C1_B_STRIDE;
            unsigned short* bld = BlS + sp * C1_B_STRIDE;
            #pragma unroll
            for (int i = 0; i < 2; i++) {
                int r = ar0 + i * 64;
                cpa16(ahd + r * WPIT + ac, g_w1h + (cob + r) * CIN + k0 + ac);
                cpa16(ald + r * WPIT + ac, g_w1l + (cob + r) * CIN + k0 + ac);
            }
            #pragma unroll
            for (int i = 0; i < 2; i++) {
                int r = br0 + i * 16;
                cpa16(bhd + r * BPIT128 + bc, xh + (k0 + r) * HW + p0 + bc);
                cpa16(bld + r * BPIT128 + bc, xl + (k0 + r) * HW + p0 + bc);
            }
        }
        cpa_commit();
        const unsigned short* ahs = AhS + s * C1_A_STRIDE;
        const unsigned short* als = AlS + s * C1_A_STRIDE;
        const unsigned short* bhs = BhS + s * C1_B_STRIDE;
        const unsigned short* bls = BlS + s * C1_B_STRIDE;
        #pragma unroll
        for (int ks = 0; ks < 2; ks++) {
            const int kb = ks * 16;
            unsigned ah[2][4];
            unsigned al[2][4];
            unsigned bh[8][2];
            unsigned bl[8][2];
            #pragma unroll
            for (int mt = 0; mt < 2; mt++) {
                load_a_frag(ah[mt], ahs, WPIT, m0 + mt * 16, kb, lane);
                load_a_frag(al[mt], als, WPIT, m0 + mt * 16, kb, lane);
            }
            #pragma unroll
            for (int hf = 0; hf < 4; hf++) {
                load_b_frag(bh[hf * 2], bh[hf * 2 + 1], bhs, BPIT128, kb, n0 + hf * 16, lane);
                load_b_frag(bl[hf * 2], bl[hf * 2 + 1], bls, BPIT128, kb, n0 + hf * 16, lane);
            }
            #pragma unroll
            for (int mt = 0; mt < 2; mt++) {
                #pragma unroll
                for (int nf = 0; nf < 8; nf++) {
                    mma16816(acc[mt][nf], ah[mt], bh[nf]);
                    mma16816(acc[mt][nf], ah[mt], bl[nf]);
                    mma16816(acc[mt][nf], al[mt], bh[nf]);
                }
            }
        }
        s = (s + 1) % 3;
        sp = (sp + 1) % 3;
    }
    #pragma unroll
    for (int mt = 0; mt < 2; mt++) {
        int co = cob + m0 + mt * 16 + (lane >> 2);
        float bv0 = bias[co];
        float bv8 = bias[co + 8];
        #pragma unroll
        for (int nf = 0; nf < 8; nf++) {
            int p = p0 + n0 + nf * 8 + 2 * (lane & 3);
            float2 v0;
            v0.x = acc[mt][nf][0] + bv0;
            v0.y = acc[mt][nf][1] + bv0;
            float2 v1;
            v1.x = acc[mt][nf][2] + bv8;
            v1.y = acc[mt][nf][3] + bv8;
            *(float2*)&g_f1[(bz * C1 + co) * HW + p] = v0;
            *(float2*)&g_f1[(bz * C1 + co + 8) * HW + p] = v1;
        }
    }
}

// ---------------- BN2 finalize + zero pad (fp16 quad + fp16 plane) ----------
__device__ __forceinline__ float bn2v(int j, float a, float b) {
    int pp = j % HPWP;
    int bc = j / HPWP;
    int y = pp / HP;
    int xx = pp % HP;
    float v = 0.f;
    if (y >= 1 && y <= H && xx >= 1 && xx <= W) {
        v = fmaf(a, g_f1[bc * HW + (y - 1) * W + (xx - 1)], b);
    }
    return v;
}

__global__ void pad_bn2_kernel(const float* __restrict__ gamma,
                               const float* __restrict__ beta) {
    int i = blockIdx.x * blockDim.x + threadIdx.x;
    if (i >= F2TOT) {
        return;
    }
    int c = (i / HPWP) % C1;
    const float inv = 1.f / (float)(BATCH * HW);
    float mean = g_s2[2 * c] * inv;
    float var = g_s2[2 * c + 1] * inv - mean * mean;
    float a = gamma[c] * rsqrtf(var + EPSV);
    float b = beta[c] - mean * a;
    float v0 = bn2v(i, a, b);
    float v1 = (i + 1 < F2TOT) ? bn2v(i + 1, a, b) : 0.f;
    float v2 = (i + HP < F2TOT) ? bn2v(i + HP, a, b) : 0.f;
    float v3 = (i + HP + 1 < F2TOT) ? bn2v(i + HP + 1, a, b) : 0.f;
    unsigned short h0 = h16(v0);
    unsigned short h1 = h16(v1);
    unsigned short h2 = h16(v2);
    unsigned short h3 = h16(v3);
    uint2 q;
    q.x = (unsigned)h0 | ((unsigned)h1 << 16);
    q.y = (unsigned)h2 | ((unsigned)h3 << 16);
    g_f2q[i] = q;
    g_f2h[i] = h0;
}

// ---------------- offconv: 32(co) x 128(px), 2-term, 1 sync/chunk ----------
__global__ __launch_bounds__(256) void offconv_kernel() {
    __shared__ unsigned short Ah[2][32][WPIT];
    __shared__ unsigned short Al[2][32][WPIT];
    __shared__ unsigned short Bs[2][32][BPIT128];
    const int bz = blockIdx.z;
    const int p0 = blockIdx.x * 128;
    const int t = threadIdx.x;
    const int lane = t & 31;
    const int wid = t >> 5;
    const int n0 = wid * 16;
    const unsigned short* __restrict__ f2hb = g_f2h + (size_t)bz * C1 * HPWP;

    const int tt = t & 127;
    const int far_ = tt >> 2;
    const int fac = (tt & 3) * 8;
    const int bj = t & 127;
    const int bk0 = t >> 7;
    const int bpy = (p0 + bj) / W;
    const int bpx = (p0 + bj) % W;
    const int boff = bpy * HP + bpx;

    float acc[2][2][4];
    #pragma unroll
    for (int mt = 0; mt < 2; mt++) {
        #pragma unroll
        for (int nt = 0; nt < 2; nt++) {
            #pragma unroll
            for (int q = 0; q < 4; q++) {
                acc[mt][nt][q] = 0.f;
            }
        }
    }

    unsigned short nb[16];
    {
        const unsigned short* src = f2hb + boff;
        #pragma unroll
        for (int i = 0; i < 16; i++) {
            int kk = bk0 + 2 * i;
            nb[i] = src[kk * HPWP];
        }
        if (t < 128) {
            cpa16(&Ah[0][far_][fac], g_w6h + far_ * KTOT + fac);
        } else {
            cpa16(&Al[0][far_][fac], g_w6l + far_ * KTOT + fac);
        }
        cpa_commit();
    }

    for (int cc = 0; cc < 72; cc++) {
        const int s = cc & 1;
        cpa_wait0();
        #pragma unroll
        for (int i = 0; i < 16; i++) {
            int kk = bk0 + 2 * i;
            Bs[s][kk][bj] = nb[i];
        }
        __syncthreads();
        if (cc < 71) {
            const int nc = cc + 1;
            const int tap = nc >> 3;
            const int ci0 = (nc & 7) * 32;
            const int dr = tap / 3;
            const int dc = tap % 3;
            const int kg = tap * C1 + ci0;
            const unsigned short* src = f2hb + boff + dr * HP + dc + ci0 * HPWP;
            #pragma unroll
            for (int i = 0; i < 16; i++) {
                int kk = bk0 + 2 * i;
                nb[i] = src[kk * HPWP];
            }
            if (t < 128) {
                cpa16(&Ah[s ^ 1][far_][fac], g_w6h + far_ * KTOT + kg + fac);
            } else {
                cpa16(&Al[s ^ 1][far_][fac], g_w6l + far_ * KTOT + kg + fac);
            }
        }
        cpa_commit();
        #pragma unroll
        for (int ks = 0; ks < 2; ks++) {
            const int kb = ks * 16;
            unsigned ah[2][4];
            unsigned al[2][4];
            unsigned bb[2][2];
            #pragma unroll
            for (int mt = 0; mt < 2; mt++) {
                load_a_frag(ah[mt], &Ah[s][0][0], WPIT, mt * 16, kb, lane);
                load_a_frag(al[mt], &Al[s][0][0], WPIT, mt * 16, kb, lane);
            }
            load_b_frag(bb[0], bb[1], &Bs[s][0][0], BPIT128, kb, n0, lane);
            #pragma unroll
            for (int mt = 0; mt < 2; mt++) {
                #pragma unroll
                for (int nt = 0; nt < 2; nt++) {
                    mma16816(acc[mt][nt], ah[mt], bb[nt]);
                    mma16816(acc[mt][nt], al[mt], bb[nt]);
                }
            }
        }
    }
    #pragma unroll
    for (int mt = 0; mt < 2; mt++) {
        #pragma unroll
        for (int hf = 0; hf < 2; hf++) {
            int co = mt * 16 + hf * 8 + (lane >> 2);
            if (co < COFF) {
                float bv = g_biasC[co];
                #pragma unroll
                for (int nt = 0; nt < 2; nt++) {
                    int p = p0 + n0 + nt * 8 + 2 * (lane & 3);
                    #pragma unroll
                    for (int q = 0; q < 2; q++) {
                        float v = acc[mt][nt][hf * 2 + q] + bv;
                        if (co >= 18 && co < 27) {
                            v = 1.f / (1.f + expf(-v));
                        } else if (co == 27) {
                            v = 2.f / (1.f + expf(-v));
                        }
                        g_off[(bz * COFF + co) * HW + p + q] = v;
                    }
                }
            }
        }
    }
}

// ---------------- deform: 64(o) x 128(px), 2-term, fp16 quad gather --------
// dyn smem layout (bytes):
//   gw  float4[1152]  @ 0       (18432)
//   gi  int   [1152]  @ 18432   (4608)
//   Ah  us[2][64][40] @ 23040   (10240)
//   Al                @ 33280   (10240)
//   Bh  us[2][32][136]@ 43520   (17408)  -> total 60928
#define DEF_SMEM 60928

__global__ __launch_bounds__(256) void deform_kernel(float* __restrict__ out) {
    extern __shared__ char smr[];
    float4* gwS = (float4*)smr;
    int* giS = (int*)(smr + 18432);
    unsigned short* AhS = (unsigned short*)(smr + 23040);
    unsigned short* AlS = (unsigned short*)(smr + 33280);
    unsigned short* BhS = (unsigned short*)(smr + 43520);

    const int bz = blockIdx.z;
    const int p0 = blockIdx.x * 128;
    const int t = threadIdx.x;
    const int lane = t & 31;
    const int wid = t >> 5;
    const int m0 = (wid >> 2) * 32;
    const int n0 = (wid & 3) * 32;
    const float* __restrict__ offb = g_off + (size_t)bz * COFF * HW;
    const uint2* __restrict__ f2qb = g_f2q + (size_t)bz * C1 * HPWP;

    // geometry: 128 px x 9 taps, quad bilinear with full clamp folding
    for (int e = t; e < 128 * NS; e += 256) {
        int j = e / NS;
        int n = e % NS;
        int p = p0 + j;
        int row = p / W;
        int col = p % W;
        float s = offb[27 * HW + p];
        float m = offb[(18 + n) * HW + p];
        float ox = offb[n * HW + p];
        float oy = offb[(9 + n) * HW + p];
        float fpx = (float)(row + 1) + 6.f * s * (float)(n / 3 - 1) + ox;
        float fpy = (float)(col + 1) + 6.f * s * (float)(n % 3 - 1) + oy;
        float fx = floorf(fpx);
        float fy = floorf(fpy);
        float qxl = fminf(fmaxf(fx, 0.f), 97.f);
        float qxr = fminf(fmaxf(fx + 1.f, 0.f), 97.f);
        float qyl = fminf(fmaxf(fy, 0.f), 97.f);
        float qyr = fminf(fmaxf(fy + 1.f, 0.f), 97.f);
        float pxc = fminf(fmaxf(fpx, 0.f), 97.f);
        float pyc = fminf(fmaxf(fpy, 0.f), 97.f);
        float ax0 = (1.f + (qxl - pxc)) * m;
        float ax1 = (1.f - (qxr - pxc)) * m;
        int cxl = (int)qxl;
        int cxr = (int)qxr;
        int bx;
        if (cxr > cxl) {
            bx = cxl;
        } else if (cxl == 0) {
            bx = 0;
            ax0 = ax0 + ax1;
            ax1 = 0.f;
        } else {
            bx = 96;
            ax1 = ax0 + ax1;
            ax0 = 0.f;
        }
        float wyl = 1.f + (qyl - pyc);
        float wyr = 1.f - (qyr - pyc);
        int cyl = (int)qyl;
        int cyr = (int)qyr;
        int cy;
        float w0;
        float w1;
        if (cyr > cyl) {
            cy = cyl;
            w0 = wyl;
            w1 = wyr;
        } else if (cyl == 0) {
            cy = 0;
            w0 = wyl + wyr;
            w1 = 0.f;
        } else {
            cy = 96;
            w0 = 0.f;
            w1 = wyl + wyr;
        }
        gwS[e] = make_float4(ax0 * w0, ax0 * w1, ax1 * w0, ax1 * w1);
        giS[e] = bx * HP + cy;
    }
    __syncthreads();

    const int far_ = t >> 2;
    const int fac = (t & 3) * 8;
    const int bj = t & 127;
    const int bk0 = t >> 7;

    float acc[2][4][4];
    #pragma unroll
    for (int mt = 0; mt < 2; mt++) {
        #pragma unroll
        for (int nt = 0; nt < 4; nt++) {
            #pragma unroll
            for (int q = 0; q < 4; q++) {
                acc[mt][nt][q] = 0.f;
            }
        }
    }

    uint2 nq[16];
    float4 cw;
    {
        int g = bj * NS;
        float4 w4 = gwS[g];
        int ib = giS[g];
        #pragma unroll
        for (int i = 0; i < 16; i++) {
            int kk = bk0 + 2 * i;
            nq[i] = f2qb[kk * HPWP + ib];
        }
        cw = w4;
        cpa16(&AhS[far_ * WPIT + fac], g_w7h + far_ * KTOT + fac);
        cpa16(&AlS[far_ * WPIT + fac], g_w7l + far_ * KTOT + fac);
        cpa_commit();
    }

    for (int cc = 0; cc < 72; cc++) {
        const int s = cc & 1;
        const int sa = s * 64 * WPIT;
        const int sb = s * 32 * BPIT128;
        cpa_wait0();
        #pragma unroll
        for (int i = 0; i < 16; i++) {
            int kk = bk0 + 2 * i;
            float2 r0 = __half22float2(*reinterpret_cast<const __half2*>(&nq[i].x));
            float2 r1 = __half22float2(*reinterpret_cast<const __half2*>(&nq[i].y));
            float v = cw.x * r0.x + cw.y * r0.y + cw.z * r1.x + cw.w * r1.y;
            BhS[sb + kk * BPIT128 + bj] = h16(v);
        }
        __syncthreads();
        if (cc < 71) {
            const int nc = cc + 1;
            const int nn = nc >> 3;
            const int ci0 = (nc & 7) * 32;
            const int kg = nn * C1 + ci0;
            int g = bj * NS + nn;
            float4 w4 = gwS[g];
            int ib = giS[g];
            const uint2* plb = f2qb + ci0 * HPWP;
            #pragma unroll
            for (int i = 0; i < 16; i++) {
                int kk = bk0 + 2 * i;
                nq[i] = plb[kk * HPWP + ib];
            }
            cw = w4;
            const int na = (s ^ 1) * 64 * WPIT;
            cpa16(&AhS[na + far_ * WPIT + fac], g_w7h + far_ * KTOT + kg + fac);
            cpa16(&AlS[na + far_ * WPIT + fac], g_w7l + far_ * KTOT + kg + fac);
        }
        cpa_commit();
        #pragma unroll
        for (int ks = 0; ks < 2; ks++) {
            const int kb = ks * 16;
            unsigned ah[2][4];
            unsigned al[2][4];
            unsigned bh[4][2];
            #pragma unroll
            for (int mt = 0; mt < 2; mt++) {
                load_a_frag(ah[mt], AhS + sa, WPIT, m0 + mt * 16, kb, lane);
                load_a_frag(al[mt], AlS + sa, WPIT, m0 + mt * 16, kb, lane);
            }
            #pragma unroll
            for (int hf = 0; hf < 2; hf++) {
                load_b_frag(bh[hf * 2], bh[hf * 2 + 1], BhS + sb, BPIT128, kb, n0 + hf * 16, lane);
            }
            #pragma unroll
            for (int mt = 0; mt < 2; mt++) {
                #pragma unroll
                for (int nt = 0; nt < 4; nt++) {
                    mma16816(acc[mt][nt], ah[mt], bh[nt]);
                    mma16816(acc[mt][nt], al[mt], bh[nt]);
                }
            }
        }
    }
    #pragma unroll
    for (int mt = 0; mt < 2; mt++) {
        int o = m0 + mt * 16 + (lane >> 2);
        #pragma unroll
        for (int nt = 0; nt < 4; nt++) {
            int p = p0 + n0 + nt * 8 + 2 * (lane & 3);
            float2 v0;
            v0.x = acc[mt][nt][0];
            v0.y = acc[mt][nt][1];
            float2 v1;
            v1.x = acc[mt][nt][2];
            v1.y = acc[mt][nt][3];
            *(float2*)&out[(bz * C2 + o) * HW + p] = v0;
            *(float2*)&out[(bz * C2 + o + 8) * HW + p] = v1;
        }
    }
}

// ---------------- launch ----------------
extern "C" void kernel_launch(void* const* d_in, const int* in_sizes, int n_in,
                              void* d_out, int out_size) {
    const float* x = (const float*)d_in[0];
    const float* bn1_g = (const float*)d_in[1];
    const float* bn1_b = (const float*)d_in[2];
    const float* w1 = (const float*)d_in[3];
    const float* b1 = (const float*)d_in[4];
    const float* bn2_g = (const float*)d_in[5];
    const float* bn2_b = (const float*)d_in[6];
    const float* pw = (const float*)d_in[7];
    const float* pb = (const float*)d_in[8];
    const float* mw = (const float*)d_in[9];
    const float* mb = (const float*)d_in[10];
    const float* dw = (const float*)d_in[11];
    const float* db = (const float*)d_in[12];
    const float* w7 = (const float*)d_in[13];
    float* out = (float*)d_out;

    cudaFuncSetAttribute(conv1_kernel, cudaFuncAttributeMaxDynamicSharedMemorySize, C1_SMEM);
    cudaFuncSetAttribute(deform_kernel, cudaFuncAttributeMaxDynamicSharedMemorySize, DEF_SMEM);

    prep_kernel<<<(C2 * KTOT + 255) / 256, 256>>>(w1, pw, pb, mw, mb, dw, db, w7);
    bn1_partial_kernel<<<dim3(CIN, 4), 256>>>(x);
    xcvt_kernel<<<(BATCH * CIN * HW / 4 + 255) / 256, 256>>>(x, bn1_g, bn1_b);
    conv1_kernel<<<dim3(HW / 128, C1 / 128, BATCH), 256, C1_SMEM>>>(b1);
    bn2_partial_kernel<<<dim3(C1, 4), 256>>>();
    pad_bn2_kernel<<<(F2TOT + 255) / 256, 256>>>(bn2_g, bn2_b);
    offconv_kernel<<<dim3(HW / 128, 1, BATCH), 256>>>();
    deform_kernel<<<dim3(HW / 128, 1, BATCH), 256, DEF_SMEM>>>(out);
}

// round 16
// speedup vs baseline: 1.0227x; 1.0227x over previous
#include <cuda_runtime.h>
#include <cuda_fp16.h>
#include <math.h>

#define H   96
#define W   96
#define HW  9216
#define HP  98
#define HPWP 9604
#define CIN 512
#define C1  256
#define C2  64
#define BATCH 2
#define NS  9
#define COFF 28
#define KTOT (C1*NS)
#define EPSV 1e-5f
#define F2TOT (BATCH * C1 * HPWP)

#define WPIT 40
#define BPIT128 136

// conv1 dynamic smem layout (3-stage)
#define C1_A_STRIDE (128 * WPIT)
#define C1_B_STRIDE (32 * BPIT128)
#define C1SM_AH 0
#define C1SM_AL (C1SM_AH + 3 * C1_A_STRIDE * 2)
#define C1SM_BH (C1SM_AL + 3 * C1_A_STRIDE * 2)
#define C1SM_BL (C1SM_BH + 3 * C1_B_STRIDE * 2)
#define C1_SMEM (C1SM_BL + 3 * C1_B_STRIDE * 2)

// fused offconv+deform smem layout (bytes)
//   offS  float[28][128]   @ 0      (14336)  persists across phases
//   phase1: A1h us[2][32][40] @14336 (5120); A1l @19456 (5120); B1 us[2][32][136] @24576 (17408) -> end 41984
//   phase2: gw float4[1152] @14336 (18432); gi int2[1152] @32768 (9216);
//           A2h us[2][64][40] @41984 (10240); A2l @52224 (10240); B2 us[2][32][136] @62464 (17408) -> 79872
#define FD_SMEM 79872

// ---------------- scratch ----------------
__device__ float g_f1[BATCH * C1 * HW];
__device__ unsigned g_f2e[F2TOT + 2];               // half2 (v[i], v[i+1]) pair plane, deform gather
__device__ unsigned short g_f2h[F2TOT];             // single fp16 plane, offconv B
__device__ unsigned short g_xh[BATCH * CIN * HW];
__device__ unsigned short g_xl[BATCH * CIN * HW];
__device__ float g_s1[CIN * 2];
__device__ float g_s2[C1 * 2];
__device__ float g_biasC[32];
__device__ unsigned short g_w1h[C1 * CIN];
__device__ unsigned short g_w1l[C1 * CIN];
__device__ unsigned short g_w6h[32 * KTOT];
__device__ unsigned short g_w6l[32 * KTOT];
__device__ unsigned short g_w7h[C2 * KTOT];
__device__ unsigned short g_w7l[C2 * KTOT];

// ---------------- helpers ----------------
__device__ __forceinline__ void splith(float v, unsigned short* hp, unsigned short* lp) {
    __half h = __float2half(v);
    float hf = __half2float(h);
    __half l = __float2half(v - hf);
    *hp = __half_as_ushort(h);
    *lp = __half_as_ushort(l);
}

__device__ __forceinline__ unsigned short h16(float v) {
    return __half_as_ushort(__float2half(v));
}

__device__ __forceinline__ unsigned smaddr(const void* p) {
    return (unsigned)__cvta_generic_to_shared(p);
}

__device__ __forceinline__ void cpa16(void* dst, const void* src) {
    asm volatile("cp.async.cg.shared.global [%0], [%1], 16;"
                 :: "r"(smaddr(dst)), "l"(src));
}
__device__ __forceinline__ void cpa_commit() {
    asm volatile("cp.async.commit_group;");
}
__device__ __forceinline__ void cpa_wait0() {
    asm volatile("cp.async.wait_group 0;");
}
__device__ __forceinline__ void cpa_wait1() {
    asm volatile("cp.async.wait_group 1;");
}

__device__ __forceinline__ void ldsm4(unsigned* r, unsigned a) {
    asm volatile("ldmatrix.sync.aligned.m8n8.x4.shared.b16 {%0,%1,%2,%3}, [%4];"
                 : "=r"(r[0]), "=r"(r[1]), "=r"(r[2]), "=r"(r[3])
                 : "r"(a));
}

__device__ __forceinline__ void ldsm4t(unsigned* r, unsigned a) {
    asm volatile("ldmatrix.sync.aligned.m8n8.x4.trans.shared.b16 {%0,%1,%2,%3}, [%4];"
                 : "=r"(r[0]), "=r"(r[1]), "=r"(r[2]), "=r"(r[3])
                 : "r"(a));
}

__device__ __forceinline__ void mma16816(float* c, const unsigned* a, const unsigned* b) {
    asm volatile("mma.sync.aligned.m16n8k16.row.col.f32.f16.f16.f32 "
                 "{%0,%1,%2,%3}, {%4,%5,%6,%7}, {%8,%9}, {%0,%1,%2,%3};"
                 : "+f"(c[0]), "+f"(c[1]), "+f"(c[2]), "+f"(c[3])
                 : "r"(a[0]), "r"(a[1]), "r"(a[2]), "r"(a[3]), "r"(b[0]), "r"(b[1]));
}

__device__ __forceinline__ void load_a_frag(unsigned* a, const unsigned short* base,
                                            int pitch, int row0, int kb, int lane) {
    const unsigned short* p = base + (row0 + (lane & 15)) * pitch + kb + ((lane >> 4) * 8);
    ldsm4(a, smaddr(p));
}

__device__ __forceinline__ void load_b_frag(unsigned b0[2], unsigned b1[2],
                                            const unsigned short* base,
                                            int pitch, int kb, int n0, int lane) {
    unsigned tmp[4];
    const unsigned short* p = base + (kb + (lane & 15)) * pitch + n0 + ((lane >> 4) * 8);
    ldsm4t(tmp, smaddr(p));
    b0[0] = tmp[0];
    b0[1] = tmp[1];
    b1[0] = tmp[2];
    b1[1] = tmp[3];
}

// ---------------- weight prep (+ zero stat accumulators each replay) --------
__global__ void prep_kernel(const float* __restrict__ w1,
                            const float* __restrict__ pw, const float* __restrict__ pb,
                            const float* __restrict__ mw, const float* __restrict__ mb,
                            const float* __restrict__ dw, const float* __restrict__ db,
                            const float* __restrict__ w7) {
    int i = blockIdx.x * blockDim.x + threadIdx.x;
    if (i < CIN * 2) {
        g_s1[i] = 0.f;
    }
    if (i < C1 * 2) {
        g_s2[i] = 0.f;
    }
    if (i < C1 * CIN) {
        splith(w1[i], &g_w1h[i], &g_w1l[i]);
    }
    if (i < 32 * KTOT) {
        int co = i / KTOT;
        int k = i % KTOT;
        int r = k / C1;
        int ci = k % C1;
        float v = 0.f;
        if (co < 18) {
            v = pw[(co * C1 + ci) * NS + r];
        } else if (co < 27) {
            v = mw[((co - 18) * C1 + ci) * NS + r];
        } else if (co == 27) {
            v = dw[ci * NS + r];
        }
        splith(v, &g_w6h[i], &g_w6l[i]);
    }
    if (i < C2 * KTOT) {
        int o = i / KTOT;
        int k = i % KTOT;
        int n = k / C1;
        int ci = k % C1;
        splith(w7[(o * C1 + ci) * NS + n], &g_w7h[i], &g_w7l[i]);
    }
    if (i < 32) {
        float v = 0.f;
        if (i < 18) {
            v = pb[i];
        } else if (i < 27) {
            v = mb[i - 18];
        } else if (i == 27) {
            v = db[0];
        }
        g_biasC[i] = v;
    }
}

// ---------------- BN partial sums (atomic, 4-way) ----------------
__device__ __forceinline__ void bn_partial_reduce(float s, float s2, float* sh,
                                                  float* dst, int c) {
    sh[threadIdx.x] = s;
    sh[256 + threadIdx.x] = s2;
    __syncthreads();
    for (int st = 128; st > 0; st >>= 1) {
        if (threadIdx.x < st) {
            sh[threadIdx.x] += sh[threadIdx.x + st];
            sh[256 + threadIdx.x] += sh[256 + threadIdx.x + st];
        }
        __syncthreads();
    }
    if (threadIdx.x == 0) {
        atomicAdd(&dst[2 * c], sh[0]);
        atomicAdd(&dst[2 * c + 1], sh[256]);
    }
}

__global__ void bn1_partial_kernel(const float* __restrict__ x) {
    __shared__ float sh[512];
    int c = blockIdx.x;
    int part = blockIdx.y;
    int bb = part >> 1;
    int hf = part & 1;
    const float4* pl = (const float4*)(x + ((size_t)(bb * CIN + c)) * HW) + hf * (HW / 8);
    float s = 0.f;
    float s2 = 0.f;
    for (int q = threadIdx.x; q < HW / 8; q += 256) {
        float4 v = pl[q];
        s += v.x + v.y + v.z + v.w;
        s2 += v.x * v.x + v.y * v.y + v.z * v.z + v.w * v.w;
    }
    bn_partial_reduce(s, s2, sh, g_s1, c);
}

__global__ void bn2_partial_kernel() {
    __shared__ float sh[512];
    int c = blockIdx.x;
    int part = blockIdx.y;
    int bb = part >> 1;
    int hf = part & 1;
    const float4* pl = (const float4*)(g_f1 + ((size_t)(bb * C1 + c)) * HW) + hf * (HW / 8);
    float s = 0.f;
    float s2 = 0.f;
    for (int q = threadIdx.x; q < HW / 8; q += 256) {
        float4 v = pl[q];
        s += v.x + v.y + v.z + v.w;
        s2 += v.x * v.x + v.y * v.y + v.z * v.z + v.w * v.w;
    }
    bn_partial_reduce(s, s2, sh, g_s2, c);
}

// ---------------- xcvt: BN1 finalize + ReLU + fp16 split ----------------
__global__ void xcvt_kernel(const float* __restrict__ x,
                            const float* __restrict__ gamma,
                            const float* __restrict__ beta) {
    int i4 = blockIdx.x * blockDim.x + threadIdx.x;
    if (i4 >= BATCH * CIN * HW / 4) {
        return;
    }
    int c = (i4 * 4 / HW) % CIN;
    const float inv = 1.f / (float)(BATCH * HW);
    float mean = g_s1[2 * c] * inv;
    float var = g_s1[2 * c + 1] * inv - mean * mean;
    float a = gamma[c] * rsqrtf(var + EPSV);
    float b = beta[c] - mean * a;
    float4 v = ((const float4*)x)[i4];
    ushort4 oh;
    ushort4 ol;
    splith(fmaxf(fmaf(a, v.x, b), 0.f), &oh.x, &ol.x);
    splith(fmaxf(fmaf(a, v.y, b), 0.f), &oh.y, &ol.y);
    splith(fmaxf(fmaf(a, v.z, b), 0.f), &oh.z, &ol.z);
    splith(fmaxf(fmaf(a, v.w, b), 0.f), &oh.w, &ol.w);
    ((ushort4*)g_xh)[i4] = oh;
    ((ushort4*)g_xl)[i4] = ol;
}

// ---------------- conv1: 128x128, 3-stage, 1 sync/chunk (proven) -----------
__global__ __launch_bounds__(256) void conv1_kernel(const float* __restrict__ bias) {
    extern __shared__ char smc[];
    unsigned short* AhS = (unsigned short*)(smc + C1SM_AH);
    unsigned short* AlS = (unsigned short*)(smc + C1SM_AL);
    unsigned short* BhS = (unsigned short*)(smc + C1SM_BH);
    unsigned short* BlS = (unsigned short*)(smc + C1SM_BL);
    const int bz = blockIdx.z;
    const int p0 = blockIdx.x * 128;
    const int cob = blockIdx.y * 128;
    const int t = threadIdx.x;
    const int lane = t & 31;
    const int wid = t >> 5;
    const int m0 = (wid >> 1) * 32;
    const int n0 = (wid & 1) * 64;
    const unsigned short* __restrict__ xh = g_xh + (size_t)bz * CIN * HW;
    const unsigned short* __restrict__ xl = g_xl + (size_t)bz * CIN * HW;

    const int ar0 = t >> 2;
    const int ac = (t & 3) * 8;
    const int br0 = t >> 4;
    const int bc = (t & 15) * 8;

    float acc[2][8][4];
    #pragma unroll
    for (int mt = 0; mt < 2; mt++) {
        #pragma unroll
        for (int nf = 0; nf < 8; nf++) {
            #pragma unroll
            for (int q = 0; q < 4; q++) {
                acc[mt][nf][q] = 0.f;
            }
        }
    }

    #pragma unroll
    for (int pc = 0; pc < 2; pc++) {
        const int k0 = pc * 32;
        unsigned short* ahd = AhS + pc * C1_A_STRIDE;
        unsigned short* ald = AlS + pc * C1_A_STRIDE;
        unsigned short* bhd = BhS + pc * C1_B_STRIDE;
        unsigned short* bld = BlS + pc * C1_B_STRIDE;
        #pragma unroll
        for (int i = 0; i < 2; i++) {
            int r = ar0 + i * 64;
            cpa16(ahd + r * WPIT + ac, g_w1h + (cob + r) * CIN + k0 + ac);
            cpa16(ald + r * WPIT + ac, g_w1l + (cob + r) * CIN + k0 + ac);
        }
        #pragma unroll
        for (int i = 0; i < 2; i++) {
            int r = br0 + i * 16;
            cpa16(bhd + r * BPIT128 + bc, xh + (k0 + r) * HW + p0 + bc);
            cpa16(bld + r * BPIT128 + bc, xl + (k0 + r) * HW + p0 + bc);
        }
        cpa_commit();
    }

    int s = 0;
    int sp = 2;
    for (int cc = 0; cc < 16; cc++) {
        cpa_wait1();
        __syncthreads();
        if (cc < 14) {
            const int k0 = (cc + 2) * 32;
            unsigned short* ahd = AhS + sp * C1_A_STRIDE;
            unsigned short* ald = AlS + sp * C1_A_STRIDE;
            unsigned short* bhd = BhS + sp * C1_B_STRIDE;
            unsigned short* bld = BlS + sp * C1_B_STRIDE;
            #pragma unroll
            for (int i = 0; i < 2; i++) {
                int r = ar0 + i * 64;
                cpa16(ahd + r * WPIT + ac, g_w1h + (cob + r) * CIN + k0 + ac);
                cpa16(ald + r * WPIT + ac, g_w1l + (cob + r) * CIN + k0 + ac);
            }
            #pragma unroll
            for (int i = 0; i < 2; i++) {
                int r = br0 + i * 16;
                cpa16(bhd + r * BPIT128 + bc, xh + (k0 + r) * HW + p0 + bc);
                cpa16(bld + r * BPIT128 + bc, xl + (k0 + r) * HW + p0 + bc);
            }
        }
        cpa_commit();
        const unsigned short* ahs = AhS + s * C1_A_STRIDE;
        const unsigned short* als = AlS + s * C1_A_STRIDE;
        const unsigned short* bhs = BhS + s * C1_B_STRIDE;
        const unsigned short* bls = BlS + s * C1_B_STRIDE;
        #pragma unroll
        for (int ks = 0; ks < 2; ks++) {
            const int kb = ks * 16;
            unsigned ah[2][4];
            unsigned al[2][4];
            unsigned bh[8][2];
            unsigned bl[8][2];
            #pragma unroll
            for (int mt = 0; mt < 2; mt++) {
                load_a_frag(ah[mt], ahs, WPIT, m0 + mt * 16, kb, lane);
                load_a_frag(al[mt], als, WPIT, m0 + mt * 16, kb, lane);
            }
            #pragma unroll
            for (int hf = 0; hf < 4; hf++) {
                load_b_frag(bh[hf * 2], bh[hf * 2 + 1], bhs, BPIT128, kb, n0 + hf * 16, lane);
                load_b_frag(bl[hf * 2], bl[hf * 2 + 1], bls, BPIT128, kb, n0 + hf * 16, lane);
            }
            #pragma unroll
            for (int mt = 0; mt < 2; mt++) {
                #pragma unroll
                for (int nf = 0; nf < 8; nf++) {
                    mma16816(acc[mt][nf], ah[mt], bh[nf]);
                    mma16816(acc[mt][nf], ah[mt], bl[nf]);
                    mma16816(acc[mt][nf], al[mt], bh[nf]);
                }
            }
        }
        s = (s + 1) % 3;
        sp = (sp + 1) % 3;
    }
    #pragma unroll
    for (int mt = 0; mt < 2; mt++) {
        int co = cob + m0 + mt * 16 + (lane >> 2);
        float bv0 = bias[co];
        float bv8 = bias[co + 8];
        #pragma unroll
        for (int nf = 0; nf < 8; nf++) {
            int p = p0 + n0 + nf * 8 + 2 * (lane & 3);
            float2 v0;
            v0.x = acc[mt][nf][0] + bv0;
            v0.y = acc[mt][nf][1] + bv0;
            float2 v1;
            v1.x = acc[mt][nf][2] + bv8;
            v1.y = acc[mt][nf][3] + bv8;
            *(float2*)&g_f1[(bz * C1 + co) * HW + p] = v0;
            *(float2*)&g_f1[(bz * C1 + co + 8) * HW + p] = v1;
        }
    }
}

// ---------------- BN2 finalize + zero pad (half2 pair + fp16 plane) --------
__device__ __forceinline__ float bn2v(int j, float a, float b) {
    int pp = j % HPWP;
    int bc = j / HPWP;
    int y = pp / HP;
    int xx = pp % HP;
    float v = 0.f;
    if (y >= 1 && y <= H && xx >= 1 && xx <= W) {
        v = fmaf(a, g_f1[bc * HW + (y - 1) * W + (xx - 1)], b);
    }
    return v;
}

__global__ void pad_bn2_kernel(const float* __restrict__ gamma,
                               const float* __restrict__ beta) {
    int i = blockIdx.x * blockDim.x + threadIdx.x;
    if (i >= F2TOT) {
        return;
    }
    int c = (i / HPWP) % C1;
    const float inv = 1.f / (float)(BATCH * HW);
    float mean = g_s2[2 * c] * inv;
    float var = g_s2[2 * c + 1] * inv - mean * mean;
    float a = gamma[c] * rsqrtf(var + EPSV);
    float b = beta[c] - mean * a;
    float v0 = bn2v(i, a, b);
    float v1 = (i + 1 < F2TOT) ? bn2v(i + 1, a, b) : 0.f;
    unsigned short h0 = h16(v0);
    unsigned short h1 = h16(v1);
    g_f2e[i] = (unsigned)h0 | ((unsigned)h1 << 16);
    g_f2h[i] = h0;
}

// ---------------- fused offconv + deform: one tile, two phases --------------
__global__ __launch_bounds__(256) void offdef_kernel(float* __restrict__ out) {
    extern __shared__ char smr[];
    float* offS = (float*)smr;                                   // [28][128]
    // phase 1 arrays
    unsigned short* A1h = (unsigned short*)(smr + 14336);
    unsigned short* A1l = (unsigned short*)(smr + 19456);
    unsigned short* B1 = (unsigned short*)(smr + 24576);
    // phase 2 arrays
    float4* gwS = (float4*)(smr + 14336);
    int2* giS = (int2*)(smr + 32768);
    unsigned short* A2h = (unsigned short*)(smr + 41984);
    unsigned short* A2l = (unsigned short*)(smr + 52224);
    unsigned short* B2 = (unsigned short*)(smr + 62464);

    const int bz = blockIdx.z;
    const int p0 = blockIdx.x * 128;
    const int t = threadIdx.x;
    const int lane = t & 31;
    const int wid = t >> 5;

    // ================= phase 1: offset/mod/dil conv (2-term) =================
    {
        const int n0 = wid * 16;
        const unsigned short* __restrict__ f2hb = g_f2h + (size_t)bz * C1 * HPWP;
        const int tt = t & 127;
        const int far_ = tt >> 2;
        const int fac = (tt & 3) * 8;
        const int bj = t & 127;
        const int bk0 = t >> 7;
        const int bpy = (p0 + bj) / W;
        const int bpx = (p0 + bj) % W;
        const int boff = bpy * HP + bpx;

        float acc[2][2][4];
        #pragma unroll
        for (int mt = 0; mt < 2; mt++) {
            #pragma unroll
            for (int nt = 0; nt < 2; nt++) {
                #pragma unroll
                for (int q = 0; q < 4; q++) {
                    acc[mt][nt][q] = 0.f;
                }
            }
        }

        unsigned short nb[16];
        {
            const unsigned short* src = f2hb + boff;
            #pragma unroll
            for (int i = 0; i < 16; i++) {
                int kk = bk0 + 2 * i;
                nb[i] = src[kk * HPWP];
            }
            if (t < 128) {
                cpa16(&A1h[far_ * WPIT + fac], g_w6h + far_ * KTOT + fac);
            } else {
                cpa16(&A1l[far_ * WPIT + fac], g_w6l + far_ * KTOT + fac);
            }
            cpa_commit();
        }

        for (int cc = 0; cc < 72; cc++) {
            const int s = cc & 1;
            const int sa = s * 32 * WPIT;
            const int sb = s * 32 * BPIT128;
            cpa_wait0();
            #pragma unroll
            for (int i = 0; i < 16; i++) {
                int kk = bk0 + 2 * i;
                B1[sb + kk * BPIT128 + bj] = nb[i];
            }
            __syncthreads();
            if (cc < 71) {
                const int nc = cc + 1;
                const int tap = nc >> 3;
                const int ci0 = (nc & 7) * 32;
                const int dr = tap / 3;
                const int dc = tap % 3;
                const int kg = tap * C1 + ci0;
                const unsigned short* src = f2hb + boff + dr * HP + dc + ci0 * HPWP;
                #pragma unroll
                for (int i = 0; i < 16; i++) {
                    int kk = bk0 + 2 * i;
                    nb[i] = src[kk * HPWP];
                }
                const int na = (s ^ 1) * 32 * WPIT;
                if (t < 128) {
                    cpa16(&A1h[na + far_ * WPIT + fac], g_w6h + far_ * KTOT + kg + fac);
                } else {
                    cpa16(&A1l[na + far_ * WPIT + fac], g_w6l + far_ * KTOT + kg + fac);
                }
            }
            cpa_commit();
            #pragma unroll
            for (int ks = 0; ks < 2; ks++) {
                const int kb = ks * 16;
                unsigned ah[2][4];
                unsigned al[2][4];
                unsigned bb[2][2];
                #pragma unroll
                for (int mt = 0; mt < 2; mt++) {
                    load_a_frag(ah[mt], A1h + sa, WPIT, mt * 16, kb, lane);
                    load_a_frag(al[mt], A1l + sa, WPIT, mt * 16, kb, lane);
                }
                load_b_frag(bb[0], bb[1], B1 + sb, BPIT128, kb, n0, lane);
                #pragma unroll
                for (int mt = 0; mt < 2; mt++) {
                    #pragma unroll
                    for (int nt = 0; nt < 2; nt++) {
                        mma16816(acc[mt][nt], ah[mt], bb[nt]);
                        mma16816(acc[mt][nt], al[mt], bb[nt]);
                    }
                }
            }
        }
        cpa_wait0();
        #pragma unroll
        for (int mt = 0; mt < 2; mt++) {
            #pragma unroll
            for (int hf = 0; hf < 2; hf++) {
                int co = mt * 16 + hf * 8 + (lane >> 2);
                if (co < COFF) {
                    float bv = g_biasC[co];
                    #pragma unroll
                    for (int nt = 0; nt < 2; nt++) {
                        int jl = n0 + nt * 8 + 2 * (lane & 3);
                        #pragma unroll
                        for (int q = 0; q < 2; q++) {
                            float v = acc[mt][nt][hf * 2 + q] + bv;
                            if (co >= 18 && co < 27) {
                                v = 1.f / (1.f + expf(-v));
                            } else if (co == 27) {
                                v = 2.f / (1.f + expf(-v));
                            }
                            offS[co * 128 + jl + q] = v;
                        }
                    }
                }
            }
        }
    }
    __syncthreads();

    // ================= phase 2: deform (2-term, half2 pair gather) ===========
    {
        const int m0 = (wid >> 2) * 32;
        const int n0 = (wid & 3) * 32;
        const unsigned* __restrict__ f2eb = g_f2e + (size_t)bz * C1 * HPWP;

        for (int e = t; e < 128 * NS; e += 256) {
            int j = e / NS;
            int n = e % NS;
            int p = p0 + j;
            int row = p / W;
            int col = p % W;
            float s = offS[27 * 128 + j];
            float m = offS[(18 + n) * 128 + j];
            float ox = offS[n * 128 + j];
            float oy = offS[(9 + n) * 128 + j];
            float fpx = (float)(row + 1) + 6.f * s * (float)(n / 3 - 1) + ox;
            float fpy = (float)(col + 1) + 6.f * s * (float)(n % 3 - 1) + oy;
            float fx = floorf(fpx);
            float fy = floorf(fpy);
            float qxl = fminf(fmaxf(fx, 0.f), 97.f);
            float qxr = fminf(fmaxf(fx + 1.f, 0.f), 97.f);
            float qyl = fminf(fmaxf(fy, 0.f), 97.f);
            float qyr = fminf(fmaxf(fy + 1.f, 0.f), 97.f);
            float pxc = fminf(fmaxf(fpx, 0.f), 97.f);
            float pyc = fminf(fmaxf(fpy, 0.f), 97.f);
            float a0 = (1.f + (qxl - pxc)) * m;
            float a1 = (1.f - (qxr - pxc)) * m;
            float wyl = 1.f + (qyl - pyc);
            float wyr = 1.f - (qyr - pyc);
            int cyl = (int)qyl;
            int cyr = (int)qyr;
            int cy;
            float w0;
            float w1;
            if (cyr > cyl) {
                cy = cyl;
                w0 = wyl;
                w1 = wyr;
            } else if (cyl == 0) {
                cy = 0;
                w0 = wyl + wyr;
                w1 = 0.f;
            } else {
                cy = 96;
                w0 = 0.f;
                w1 = wyl + wyr;
            }
            gwS[e] = make_float4(a0, a1, w0, w1);
            giS[e] = make_int2((int)qxl * HP + cy, (int)qxr * HP + cy);
        }
        __syncthreads();

        const int far_ = t >> 2;
        const int fac = (t & 3) * 8;
        const int bj = t & 127;
        const int bk0 = t >> 7;

        float acc[2][4][4];
        #pragma unroll
        for (int mt = 0; mt < 2; mt++) {
            #pragma unroll
            for (int nt = 0; nt < 4; nt++) {
                #pragma unroll
                for (int q = 0; q < 4; q++) {
                    acc[mt][nt][q] = 0.f;
                }
            }
        }

        unsigned nu[16];
        unsigned nv[16];
        float4 cw;
        {
            int g = bj * NS;
            float4 w4 = gwS[g];
            int2 i2 = giS[g];
            #pragma unroll
            for (int i = 0; i < 16; i++) {
                int kk = bk0 + 2 * i;
                const unsigned* pl = f2eb + kk * HPWP;
                nu[i] = pl[i2.x];
                nv[i] = pl[i2.y];
            }
            cw = w4;
            cpa16(&A2h[far_ * WPIT + fac], g_w7h + far_ * KTOT + fac);
            cpa16(&A2l[far_ * WPIT + fac], g_w7l + far_ * KTOT + fac);
            cpa_commit();
        }

        for (int cc = 0; cc < 72; cc++) {
            const int s = cc & 1;
            const int sa = s * 64 * WPIT;
            const int sb = s * 32 * BPIT128;
            cpa_wait0();
            #pragma unroll
            for (int i = 0; i < 16; i++) {
                int kk = bk0 + 2 * i;
                float2 uf = __half22float2(*reinterpret_cast<const __half2*>(&nu[i]));
                float2 vf = __half22float2(*reinterpret_cast<const __half2*>(&nv[i]));
                float t0 = cw.x * uf.x + cw.y * vf.x;
                float t1 = cw.x * uf.y + cw.y * vf.y;
                B2[sb + kk * BPIT128 + bj] = h16(cw.z * t0 + cw.w * t1);
            }
            __syncthreads();
            if (cc < 71) {
                const int nc = cc + 1;
                const int nn = nc >> 3;
                const int ci0 = (nc & 7) * 32;
                const int kg = nn * C1 + ci0;
                int g = bj * NS + nn;
                float4 w4 = gwS[g];
                int2 i2 = giS[g];
                const unsigned* plb = f2eb + ci0 * HPWP;
                #pragma unroll
                for (int i = 0; i < 16; i++) {
                    int kk = bk0 + 2 * i;
                    const unsigned* pl = plb + kk * HPWP;
                    nu[i] = pl[i2.x];
                    nv[i] = pl[i2.y];
                }
                cw = w4;
                const int na = (s ^ 1) * 64 * WPIT;
                cpa16(&A2h[na + far_ * WPIT + fac], g_w7h + far_ * KTOT + kg + fac);
                cpa16(&A2l[na + far_ * WPIT + fac], g_w7l + far_ * KTOT + kg + fac);
            }
            cpa_commit();
            #pragma unroll
            for (int ks = 0; ks < 2; ks++) {
                const int kb = ks * 16;
                unsigned ah[2][4];
                unsigned al[2][4];
                unsigned bh[4][2];
                #pragma unroll
                for (int mt = 0; mt < 2; mt++) {
                    load_a_frag(ah[mt], A2h + sa, WPIT, m0 + mt * 16, kb, lane);
                    load_a_frag(al[mt], A2l + sa, WPIT, m0 + mt * 16, kb, lane);
                }
                #pragma unroll
                for (int hf = 0; hf < 2; hf++) {
                    load_b_frag(bh[hf * 2], bh[hf * 2 + 1], B2 + sb, BPIT128, kb, n0 + hf * 16, lane);
                }
                #pragma unroll
                for (int mt = 0; mt < 2; mt++) {
                    #pragma unroll
                    for (int nt = 0; nt < 4; nt++) {
                        mma16816(acc[mt][nt], ah[mt], bh[nt]);
                        mma16816(acc[mt][nt], al[mt], bh[nt]);
                    }
                }
            }
        }
        #pragma unroll
        for (int mt = 0; mt < 2; mt++) {
            int o = m0 + mt * 16 + (lane >> 2);
            #pragma unroll
            for (int nt = 0; nt < 4; nt++) {
                int p = p0 + n0 + nt * 8 + 2 * (lane & 3);
                float2 v0;
                v0.x = acc[mt][nt][0];
                v0.y = acc[mt][nt][1];
                float2 v1;
                v1.x = acc[mt][nt][2];
                v1.y = acc[mt][nt][3];
                *(float2*)&out[(bz * C2 + o) * HW + p] = v0;
                *(float2*)&out[(bz * C2 + o + 8) * HW + p] = v1;
            }
        }
    }
}

// ---------------- launch ----------------
extern "C" void kernel_launch(void* const* d_in, const int* in_sizes, int n_in,
                              void* d_out, int out_size) {
    const float* x = (const float*)d_in[0];
    const float* bn1_g = (const float*)d_in[1];
    const float* bn1_b = (const float*)d_in[2];
    const float* w1 = (const float*)d_in[3];
    const float* b1 = (const float*)d_in[4];
    const float* bn2_g = (const float*)d_in[5];
    const float* bn2_b = (const float*)d_in[6];
    const float* pw = (const float*)d_in[7];
    const float* pb = (const float*)d_in[8];
    const float* mw = (const float*)d_in[9];
    const float* mb = (const float*)d_in[10];
    const float* dw = (const float*)d_in[11];
    const float* db = (const float*)d_in[12];
    const float* w7 = (const float*)d_in[13];
    float* out = (float*)d_out;

    cudaFuncSetAttribute(conv1_kernel, cudaFuncAttributeMaxDynamicSharedMemorySize, C1_SMEM);
    cudaFuncSetAttribute(offdef_kernel, cudaFuncAttributeMaxDynamicSharedMemorySize, FD_SMEM);

    prep_kernel<<<(C2 * KTOT + 255) / 256, 256>>>(w1, pw, pb, mw, mb, dw, db, w7);
    bn1_partial_kernel<<<dim3(CIN, 4), 256>>>(x);
    xcvt_kernel<<<(BATCH * CIN * HW / 4 + 255) / 256, 256>>>(x, bn1_g, bn1_b);
    conv1_kernel<<<dim3(HW / 128, C1 / 128, BATCH), 256, C1_SMEM>>>(b1);
    bn2_partial_kernel<<<dim3(C1, 4), 256>>>();
    pad_bn2_kernel<<<(F2TOT + 255) / 256, 256>>>(bn2_g, bn2_b);
    offdef_kernel<<<dim3(HW / 128, 1, BATCH), 256, FD_SMEM>>>(out);
}

// round 17
// speedup vs baseline: 1.0860x; 1.0618x over previous
#include <cuda_runtime.h>
#include <cuda_fp16.h>
#include <math.h>

#define H   96
#define W   96
#define HW  9216
#define HP  98
#define HPWP 9604
#define CIN 512
#define C1  256
#define C2  64
#define BATCH 2
#define NS  9
#define COFF 28
#define KTOT (C1*NS)
#define EPSV 1e-5f
#define F2TOT (BATCH * C1 * HPWP)
#define OUTN (BATCH * C2 * HW)

#define WPIT 40
#define BPIT128 136

// conv1 dynamic smem layout (3-stage)
#define C1_A_STRIDE (128 * WPIT)
#define C1_B_STRIDE (32 * BPIT128)
#define C1SM_AH 0
#define C1SM_AL (C1SM_AH + 3 * C1_A_STRIDE * 2)
#define C1SM_BH (C1SM_AL + 3 * C1_A_STRIDE * 2)
#define C1SM_BL (C1SM_BH + 3 * C1_B_STRIDE * 2)
#define C1_SMEM (C1SM_BL + 3 * C1_B_STRIDE * 2)

// ---------------- scratch ----------------
__device__ float g_f1[BATCH * C1 * HW];
__device__ unsigned g_f2e[F2TOT + 2];               // half2 (v[i], v[i+1]) pair plane, deform gather
__device__ unsigned short g_f2h[F2TOT];             // single fp16 plane, offconv B
__device__ unsigned short g_xh[BATCH * CIN * HW];
__device__ unsigned short g_xl[BATCH * CIN * HW];
__device__ float g_off[BATCH * COFF * HW];
__device__ float g_do0[OUTN];                       // deform K-split partials
__device__ float g_do1[OUTN];
__device__ float g_s1[CIN * 2];
__device__ float g_s2[C1 * 2];
__device__ float g_biasC[32];
__device__ unsigned short g_w1h[C1 * CIN];
__device__ unsigned short g_w1l[C1 * CIN];
__device__ unsigned short g_w6h[32 * KTOT];
__device__ unsigned short g_w6l[32 * KTOT];
__device__ unsigned short g_w7h[C2 * KTOT];
__device__ unsigned short g_w7l[C2 * KTOT];

// ---------------- helpers ----------------
__device__ __forceinline__ void splith(float v, unsigned short* hp, unsigned short* lp) {
    __half h = __float2half(v);
    float hf = __half2float(h);
    __half l = __float2half(v - hf);
    *hp = __half_as_ushort(h);
    *lp = __half_as_ushort(l);
}

__device__ __forceinline__ unsigned short h16(float v) {
    return __half_as_ushort(__float2half(v));
}

__device__ __forceinline__ unsigned smaddr(const void* p) {
    return (unsigned)__cvta_generic_to_shared(p);
}

__device__ __forceinline__ void cpa16(void* dst, const void* src) {
    asm volatile("cp.async.cg.shared.global [%0], [%1], 16;"
                 :: "r"(smaddr(dst)), "l"(src));
}
__device__ __forceinline__ void cpa_commit() {
    asm volatile("cp.async.commit_group;");
}
__device__ __forceinline__ void cpa_wait0() {
    asm volatile("cp.async.wait_group 0;");
}
__device__ __forceinline__ void cpa_wait1() {
    asm volatile("cp.async.wait_group 1;");
}

__device__ __forceinline__ void ldsm4(unsigned* r, unsigned a) {
    asm volatile("ldmatrix.sync.aligned.m8n8.x4.shared.b16 {%0,%1,%2,%3}, [%4];"
                 : "=r"(r[0]), "=r"(r[1]), "=r"(r[2]), "=r"(r[3])
                 : "r"(a));
}

__device__ __forceinline__ void ldsm4t(unsigned* r, unsigned a) {
    asm volatile("ldmatrix.sync.aligned.m8n8.x4.trans.shared.b16 {%0,%1,%2,%3}, [%4];"
                 : "=r"(r[0]), "=r"(r[1]), "=r"(r[2]), "=r"(r[3])
                 : "r"(a));
}

__device__ __forceinline__ void mma16816(float* c, const unsigned* a, const unsigned* b) {
    asm volatile("mma.sync.aligned.m16n8k16.row.col.f32.f16.f16.f32 "
                 "{%0,%1,%2,%3}, {%4,%5,%6,%7}, {%8,%9}, {%0,%1,%2,%3};"
                 : "+f"(c[0]), "+f"(c[1]), "+f"(c[2]), "+f"(c[3])
                 : "r"(a[0]), "r"(a[1]), "r"(a[2]), "r"(a[3]), "r"(b[0]), "r"(b[1]));
}

__device__ __forceinline__ void load_a_frag(unsigned* a, const unsigned short* base,
                                            int pitch, int row0, int kb, int lane) {
    const unsigned short* p = base + (row0 + (lane & 15)) * pitch + kb + ((lane >> 4) * 8);
    ldsm4(a, smaddr(p));
}

__device__ __forceinline__ void load_b_frag(unsigned b0[2], unsigned b1[2],
                                            const unsigned short* base,
                                            int pitch, int kb, int n0, int lane) {
    unsigned tmp[4];
    const unsigned short* p = base + (kb + (lane & 15)) * pitch + n0 + ((lane >> 4) * 8);
    ldsm4t(tmp, smaddr(p));
    b0[0] = tmp[0];
    b0[1] = tmp[1];
    b1[0] = tmp[2];
    b1[1] = tmp[3];
}

// ---------------- weight prep (+ zero stat accumulators each replay) --------
__global__ void prep_kernel(const float* __restrict__ w1,
                            const float* __restrict__ pw, const float* __restrict__ pb,
                            const float* __restrict__ mw, const float* __restrict__ mb,
                            const float* __restrict__ dw, const float* __restrict__ db,
                            const float* __restrict__ w7) {
    int i = blockIdx.x * blockDim.x + threadIdx.x;
    if (i < CIN * 2) {
        g_s1[i] = 0.f;
    }
    if (i < C1 * 2) {
        g_s2[i] = 0.f;
    }
    if (i < C1 * CIN) {
        splith(w1[i], &g_w1h[i], &g_w1l[i]);
    }
    if (i < 32 * KTOT) {
        int co = i / KTOT;
        int k = i % KTOT;
        int r = k / C1;
        int ci = k % C1;
        float v = 0.f;
        if (co < 18) {
            v = pw[(co * C1 + ci) * NS + r];
        } else if (co < 27) {
            v = mw[((co - 18) * C1 + ci) * NS + r];
        } else if (co == 27) {
            v = dw[ci * NS + r];
        }
        splith(v, &g_w6h[i], &g_w6l[i]);
    }
    if (i < C2 * KTOT) {
        int o = i / KTOT;
        int k = i % KTOT;
        int n = k / C1;
        int ci = k % C1;
        splith(w7[(o * C1 + ci) * NS + n], &g_w7h[i], &g_w7l[i]);
    }
    if (i < 32) {
        float v = 0.f;
        if (i < 18) {
            v = pb[i];
        } else if (i < 27) {
            v = mb[i - 18];
        } else if (i == 27) {
            v = db[0];
        }
        g_biasC[i] = v;
    }
}

// ---------------- BN partial sums (atomic, 4-way) ----------------
__device__ __forceinline__ void bn_partial_reduce(float s, float s2, float* sh,
                                                  float* dst, int c) {
    sh[threadIdx.x] = s;
    sh[256 + threadIdx.x] = s2;
    __syncthreads();
    for (int st = 128; st > 0; st >>= 1) {
        if (threadIdx.x < st) {
            sh[threadIdx.x] += sh[threadIdx.x + st];
            sh[256 + threadIdx.x] += sh[256 + threadIdx.x + st];
        }
        __syncthreads();
    }
    if (threadIdx.x == 0) {
        atomicAdd(&dst[2 * c], sh[0]);
        atomicAdd(&dst[2 * c + 1], sh[256]);
    }
}

__global__ void bn1_partial_kernel(const float* __restrict__ x) {
    __shared__ float sh[512];
    int c = blockIdx.x;
    int part = blockIdx.y;
    int bb = part >> 1;
    int hf = part & 1;
    const float4* pl = (const float4*)(x + ((size_t)(bb * CIN + c)) * HW) + hf * (HW / 8);
    float s = 0.f;
    float s2 = 0.f;
    for (int q = threadIdx.x; q < HW / 8; q += 256) {
        float4 v = pl[q];
        s += v.x + v.y + v.z + v.w;
        s2 += v.x * v.x + v.y * v.y + v.z * v.z + v.w * v.w;
    }
    bn_partial_reduce(s, s2, sh, g_s1, c);
}

__global__ void bn2_partial_kernel() {
    __shared__ float sh[512];
    int c = blockIdx.x;
    int part = blockIdx.y;
    int bb = part >> 1;
    int hf = part & 1;
    const float4* pl = (const float4*)(g_f1 + ((size_t)(bb * C1 + c)) * HW) + hf * (HW / 8);
    float s = 0.f;
    float s2 = 0.f;
    for (int q = threadIdx.x; q < HW / 8; q += 256) {
        float4 v = pl[q];
        s += v.x + v.y + v.z + v.w;
        s2 += v.x * v.x + v.y * v.y + v.z * v.z + v.w * v.w;
    }
    bn_partial_reduce(s, s2, sh, g_s2, c);
}

// ---------------- xcvt: BN1 finalize + ReLU + fp16 split ----------------
__global__ void xcvt_kernel(const float* __restrict__ x,
                            const float* __restrict__ gamma,
                            const float* __restrict__ beta) {
    int i4 = blockIdx.x * blockDim.x + threadIdx.x;
    if (i4 >= BATCH * CIN * HW / 4) {
        return;
    }
    int c = (i4 * 4 / HW) % CIN;
    const float inv = 1.f / (float)(BATCH * HW);
    float mean = g_s1[2 * c] * inv;
    float var = g_s1[2 * c + 1] * inv - mean * mean;
    float a = gamma[c] * rsqrtf(var + EPSV);
    float b = beta[c] - mean * a;
    float4 v = ((const float4*)x)[i4];
    ushort4 oh;
    ushort4 ol;
    splith(fmaxf(fmaf(a, v.x, b), 0.f), &oh.x, &ol.x);
    splith(fmaxf(fmaf(a, v.y, b), 0.f), &oh.y, &ol.y);
    splith(fmaxf(fmaf(a, v.z, b), 0.f), &oh.z, &ol.z);
    splith(fmaxf(fmaf(a, v.w, b), 0.f), &oh.w, &ol.w);
    ((ushort4*)g_xh)[i4] = oh;
    ((ushort4*)g_xl)[i4] = ol;
}

// ---------------- conv1: 128x128, 3-stage, 1 sync/chunk (proven) -----------
__global__ __launch_bounds__(256) void conv1_kernel(const float* __restrict__ bias) {
    extern __shared__ char smc[];
    unsigned short* AhS = (unsigned short*)(smc + C1SM_AH);
    unsigned short* AlS = (unsigned short*)(smc + C1SM_AL);
    unsigned short* BhS = (unsigned short*)(smc + C1SM_BH);
    unsigned short* BlS = (unsigned short*)(smc + C1SM_BL);
    const int bz = blockIdx.z;
    const int p0 = blockIdx.x * 128;
    const int cob = blockIdx.y * 128;
    const int t = threadIdx.x;
    const int lane = t & 31;
    const int wid = t >> 5;
    const int m0 = (wid >> 1) * 32;
    const int n0 = (wid & 1) * 64;
    const unsigned short* __restrict__ xh = g_xh + (size_t)bz * CIN * HW;
    const unsigned short* __restrict__ xl = g_xl + (size_t)bz * CIN * HW;

    const int ar0 = t >> 2;
    const int ac = (t & 3) * 8;
    const int br0 = t >> 4;
    const int bc = (t & 15) * 8;

    float acc[2][8][4];
    #pragma unroll
    for (int mt = 0; mt < 2; mt++) {
        #pragma unroll
        for (int nf = 0; nf < 8; nf++) {
            #pragma unroll
            for (int q = 0; q < 4; q++) {
                acc[mt][nf][q] = 0.f;
            }
        }
    }

    #pragma unroll
    for (int pc = 0; pc < 2; pc++) {
        const int k0 = pc * 32;
        unsigned short* ahd = AhS + pc * C1_A_STRIDE;
        unsigned short* ald = AlS + pc * C1_A_STRIDE;
        unsigned short* bhd = BhS + pc * C1_B_STRIDE;
        unsigned short* bld = BlS + pc * C1_B_STRIDE;
        #pragma unroll
        for (int i = 0; i < 2; i++) {
            int r = ar0 + i * 64;
            cpa16(ahd + r * WPIT + ac, g_w1h + (cob + r) * CIN + k0 + ac);
            cpa16(ald + r * WPIT + ac, g_w1l + (cob + r) * CIN + k0 + ac);
        }
        #pragma unroll
        for (int i = 0; i < 2; i++) {
            int r = br0 + i * 16;
            cpa16(bhd + r * BPIT128 + bc, xh + (k0 + r) * HW + p0 + bc);
            cpa16(bld + r * BPIT128 + bc, xl + (k0 + r) * HW + p0 + bc);
        }
        cpa_commit();
    }

    int s = 0;
    int sp = 2;
    for (int cc = 0; cc < 16; cc++) {
        cpa_wait1();
        __syncthreads();
        if (cc < 14) {
            const int k0 = (cc + 2) * 32;
            unsigned short* ahd = AhS + sp * C1_A_STRIDE;
            unsigned short* ald = AlS + sp * C1_A_STRIDE;
            unsigned short* bhd = BhS + sp * C1_B_STRIDE;
            unsigned short* bld = BlS + sp * C1_B_STRIDE;
            #pragma unroll
            for (int i = 0; i < 2; i++) {
                int r = ar0 + i * 64;
                cpa16(ahd + r * WPIT + ac, g_w1h + (cob + r) * CIN + k0 + ac);
                cpa16(ald + r * WPIT + ac, g_w1l + (cob + r) * CIN + k0 + ac);
            }
            #pragma unroll
            for (int i = 0; i < 2; i++) {
                int r = br0 + i * 16;
                cpa16(bhd + r * BPIT128 + bc, xh + (k0 + r) * HW + p0 + bc);
                cpa16(bld + r * BPIT128 + bc, xl + (k0 + r) * HW + p0 + bc);
            }
        }
        cpa_commit();
        const unsigned short* ahs = AhS + s * C1_A_STRIDE;
        const unsigned short* als = AlS + s * C1_A_STRIDE;
        const unsigned short* bhs = BhS + s * C1_B_STRIDE;
        const unsigned short* bls = BlS + s * C1_B_STRIDE;
        #pragma unroll
        for (int ks = 0; ks < 2; ks++) {
            const int kb = ks * 16;
            unsigned ah[2][4];
            unsigned al[2][4];
            unsigned bh[8][2];
            unsigned bl[8][2];
            #pragma unroll
            for (int mt = 0; mt < 2; mt++) {
                load_a_frag(ah[mt], ahs, WPIT, m0 + mt * 16, kb, lane);
                load_a_frag(al[mt], als, WPIT, m0 + mt * 16, kb, lane);
            }
            #pragma unroll
            for (int hf = 0; hf < 4; hf++) {
                load_b_frag(bh[hf * 2], bh[hf * 2 + 1], bhs, BPIT128, kb, n0 + hf * 16, lane);
                load_b_frag(bl[hf * 2], bl[hf * 2 + 1], bls, BPIT128, kb, n0 + hf * 16, lane);
            }
            #pragma unroll
            for (int mt = 0; mt < 2; mt++) {
                #pragma unroll
                for (int nf = 0; nf < 8; nf++) {
                    mma16816(acc[mt][nf], ah[mt], bh[nf]);
                    mma16816(acc[mt][nf], ah[mt], bl[nf]);
                    mma16816(acc[mt][nf], al[mt], bh[nf]);
                }
            }
        }
        s = (s + 1) % 3;
        sp = (sp + 1) % 3;
    }
    #pragma unroll
    for (int mt = 0; mt < 2; mt++) {
        int co = cob + m0 + mt * 16 + (lane >> 2);
        float bv0 = bias[co];
        float bv8 = bias[co + 8];
        #pragma unroll
        for (int nf = 0; nf < 8; nf++) {
            int p = p0 + n0 + nf * 8 + 2 * (lane & 3);
            float2 v0;
            v0.x = acc[mt][nf][0] + bv0;
            v0.y = acc[mt][nf][1] + bv0;
            float2 v1;
            v1.x = acc[mt][nf][2] + bv8;
            v1.y = acc[mt][nf][3] + bv8;
            *(float2*)&g_f1[(bz * C1 + co) * HW + p] = v0;
            *(float2*)&g_f1[(bz * C1 + co + 8) * HW + p] = v1;
        }
    }
}

// ---------------- BN2 finalize + zero pad (half2 pair + fp16 plane) --------
__device__ __forceinline__ float bn2v(int j, float a, float b) {
    int pp = j % HPWP;
    int bc = j / HPWP;
    int y = pp / HP;
    int xx = pp % HP;
    float v = 0.f;
    if (y >= 1 && y <= H && xx >= 1 && xx <= W) {
        v = fmaf(a, g_f1[bc * HW + (y - 1) * W + (xx - 1)], b);
    }
    return v;
}

__global__ void pad_bn2_kernel(const float* __restrict__ gamma,
                               const float* __restrict__ beta) {
    int i = blockIdx.x * blockDim.x + threadIdx.x;
    if (i >= F2TOT) {
        return;
    }
    int c = (i / HPWP) % C1;
    const float inv = 1.f / (float)(BATCH * HW);
    float mean = g_s2[2 * c] * inv;
    float var = g_s2[2 * c + 1] * inv - mean * mean;
    float a = gamma[c] * rsqrtf(var + EPSV);
    float b = beta[c] - mean * a;
    float v0 = bn2v(i, a, b);
    float v1 = (i + 1 < F2TOT) ? bn2v(i + 1, a, b) : 0.f;
    unsigned short h0 = h16(v0);
    unsigned short h1 = h16(v1);
    g_f2e[i] = (unsigned)h0 | ((unsigned)h1 << 16);
    g_f2h[i] = h0;
}

// ---------------- offconv: 32(co) x 128(px), 2-term, 1 sync/chunk ----------
__global__ __launch_bounds__(256) void offconv_kernel() {
    __shared__ unsigned short Ah[2][32][WPIT];
    __shared__ unsigned short Al[2][32][WPIT];
    __shared__ unsigned short Bs[2][32][BPIT128];
    const int bz = blockIdx.z;
    const int p0 = blockIdx.x * 128;
    const int t = threadIdx.x;
    const int lane = t & 31;
    const int wid = t >> 5;
    const int n0 = wid * 16;
    const unsigned short* __restrict__ f2hb = g_f2h + (size_t)bz * C1 * HPWP;

    const int tt = t & 127;
    const int far_ = tt >> 2;
    const int fac = (tt & 3) * 8;
    const int bj = t & 127;
    const int bk0 = t >> 7;
    const int bpy = (p0 + bj) / W;
    const int bpx = (p0 + bj) % W;
    const int boff = bpy * HP + bpx;

    float acc[2][2][4];
    #pragma unroll
    for (int mt = 0; mt < 2; mt++) {
        #pragma unroll
        for (int nt = 0; nt < 2; nt++) {
            #pragma unroll
            for (int q = 0; q < 4; q++) {
                acc[mt][nt][q] = 0.f;
            }
        }
    }

    unsigned short nb[16];
    {
        const unsigned short* src = f2hb + boff;
        #pragma unroll
        for (int i = 0; i < 16; i++) {
            int kk = bk0 + 2 * i;
            nb[i] = src[kk * HPWP];
        }
        if (t < 128) {
            cpa16(&Ah[0][far_][fac], g_w6h + far_ * KTOT + fac);
        } else {
            cpa16(&Al[0][far_][fac], g_w6l + far_ * KTOT + fac);
        }
        cpa_commit();
    }

    for (int cc = 0; cc < 72; cc++) {
        const int s = cc & 1;
        cpa_wait0();
        #pragma unroll
        for (int i = 0; i < 16; i++) {
            int kk = bk0 + 2 * i;
            Bs[s][kk][bj] = nb[i];
        }
        __syncthreads();
        if (cc < 71) {
            const int nc = cc + 1;
            const int tap = nc >> 3;
            const int ci0 = (nc & 7) * 32;
            const int dr = tap / 3;
            const int dc = tap % 3;
            const int kg = tap * C1 + ci0;
            const unsigned short* src = f2hb + boff + dr * HP + dc + ci0 * HPWP;
            #pragma unroll
            for (int i = 0; i < 16; i++) {
                int kk = bk0 + 2 * i;
                nb[i] = src[kk * HPWP];
            }
            if (t < 128) {
                cpa16(&Ah[s ^ 1][far_][fac], g_w6h + far_ * KTOT + kg + fac);
            } else {
                cpa16(&Al[s ^ 1][far_][fac], g_w6l + far_ * KTOT + kg + fac);
            }
        }
        cpa_commit();
        #pragma unroll
        for (int ks = 0; ks < 2; ks++) {
            const int kb = ks * 16;
            unsigned ah[2][4];
            unsigned al[2][4];
            unsigned bb[2][2];
            #pragma unroll
            for (int mt = 0; mt < 2; mt++) {
                load_a_frag(ah[mt], &Ah[s][0][0], WPIT, mt * 16, kb, lane);
                load_a_frag(al[mt], &Al[s][0][0], WPIT, mt * 16, kb, lane);
            }
            load_b_frag(bb[0], bb[1], &Bs[s][0][0], BPIT128, kb, n0, lane);
            #pragma unroll
            for (int mt = 0; mt < 2; mt++) {
                #pragma unroll
                for (int nt = 0; nt < 2; nt++) {
                    mma16816(acc[mt][nt], ah[mt], bb[nt]);
                    mma16816(acc[mt][nt], al[mt], bb[nt]);
                }
            }
        }
    }
    #pragma unroll
    for (int mt = 0; mt < 2; mt++) {
        #pragma unroll
        for (int hf = 0; hf < 2; hf++) {
            int co = mt * 16 + hf * 8 + (lane >> 2);
            if (co < COFF) {
                float bv = g_biasC[co];
                #pragma unroll
                for (int nt = 0; nt < 2; nt++) {
                    int p = p0 + n0 + nt * 8 + 2 * (lane & 3);
                    #pragma unroll
                    for (int q = 0; q < 2; q++) {
                        float v = acc[mt][nt][hf * 2 + q] + bv;
                        if (co >= 18 && co < 27) {
                            v = 1.f / (1.f + expf(-v));
                        } else if (co == 27) {
                            v = 2.f / (1.f + expf(-v));
                        }
                        g_off[(bz * COFF + co) * HW + p + q] = v;
                    }
                }
            }
        }
    }
}

// ---------------- deform: 64(o) x 128(px), K-split x2, half2 gather --------
#define DEF_SMEM 65536

__global__ __launch_bounds__(256) void deform_kernel() {
    extern __shared__ char smr[];
    float4* gwS = (float4*)smr;
    int2* giS = (int2*)(smr + 18432);
    unsigned short* AhS = (unsigned short*)(smr + 27648);
    unsigned short* AlS = (unsigned short*)(smr + 37888);
    unsigned short* BhS = (unsigned short*)(smr + 48128);

    const int bz = blockIdx.z;
    const int ky = blockIdx.y;
    const int c0 = ky * 36;
    const int p0 = blockIdx.x * 128;
    const int t = threadIdx.x;
    const int lane = t & 31;
    const int wid = t >> 5;
    const int m0 = (wid >> 2) * 32;
    const int n0 = (wid & 3) * 32;
    const float* __restrict__ offb = g_off + (size_t)bz * COFF * HW;
    const unsigned* __restrict__ f2eb = g_f2e + (size_t)bz * C1 * HPWP;
    float* __restrict__ dst = (ky == 0) ? g_do0 : g_do1;

    for (int e = t; e < 128 * NS; e += 256) {
        int j = e / NS;
        int n = e % NS;
        int p = p0 + j;
        int row = p / W;
        int col = p % W;
        float s = offb[27 * HW + p];
        float m = offb[(18 + n) * HW + p];
        float ox = offb[n * HW + p];
        float oy = offb[(9 + n) * HW + p];
        float fpx = (float)(row + 1) + 6.f * s * (float)(n / 3 - 1) + ox;
        float fpy = (float)(col + 1) + 6.f * s * (float)(n % 3 - 1) + oy;
        float fx = floorf(fpx);
        float fy = floorf(fpy);
        float qxl = fminf(fmaxf(fx, 0.f), 97.f);
        float qxr = fminf(fmaxf(fx + 1.f, 0.f), 97.f);
        float qyl = fminf(fmaxf(fy, 0.f), 97.f);
        float qyr = fminf(fmaxf(fy + 1.f, 0.f), 97.f);
        float pxc = fminf(fmaxf(fpx, 0.f), 97.f);
        float pyc = fminf(fmaxf(fpy, 0.f), 97.f);
        float a0 = (1.f + (qxl - pxc)) * m;
        float a1 = (1.f - (qxr - pxc)) * m;
        float wyl = 1.f + (qyl - pyc);
        float wyr = 1.f - (qyr - pyc);
        int cyl = (int)qyl;
        int cyr = (int)qyr;
        int cy;
        float w0;
        float w1;
        if (cyr > cyl) {
            cy = cyl;
            w0 = wyl;
            w1 = wyr;
        } else if (cyl == 0) {
            cy = 0;
            w0 = wyl + wyr;
            w1 = 0.f;
        } else {
            cy = 96;
            w0 = 0.f;
            w1 = wyl + wyr;
        }
        gwS[e] = make_float4(a0, a1, w0, w1);
        giS[e] = make_int2((int)qxl * HP + cy, (int)qxr * HP + cy);
    }
    __syncthreads();

    const int far_ = t >> 2;
    const int fac = (t & 3) * 8;
    const int bj = t & 127;
    const int bk0 = t >> 7;

    float acc[2][4][4];
    #pragma unroll
    for (int mt = 0; mt < 2; mt++) {
        #pragma unroll
        for (int nt = 0; nt < 4; nt++) {
            #pragma unroll
            for (int q = 0; q < 4; q++) {
                acc[mt][nt][q] = 0.f;
            }
        }
    }

    unsigned nu[16];
    unsigned nv[16];
    float4 cw;
    {
        const int nn0 = c0 >> 3;
        const int ci00 = (c0 & 7) * 32;
        const int kg0 = nn0 * C1 + ci00;
        int g = bj * NS + nn0;
        float4 w4 = gwS[g];
        int2 i2 = giS[g];
        const unsigned* plb = f2eb + ci00 * HPWP;
        #pragma unroll
        for (int i = 0; i < 16; i++) {
            int kk = bk0 + 2 * i;
            const unsigned* pl = plb + kk * HPWP;
            nu[i] = pl[i2.x];
            nv[i] = pl[i2.y];
        }
        cw = w4;
        cpa16(&AhS[far_ * WPIT + fac], g_w7h + far_ * KTOT + kg0 + fac);
        cpa16(&AlS[far_ * WPIT + fac], g_w7l + far_ * KTOT + kg0 + fac);
        cpa_commit();
    }

    for (int cc = c0; cc < c0 + 36; cc++) {
        const int s = cc & 1;
        const int sa = s * 64 * WPIT;
        const int sb = s * 32 * BPIT128;
        cpa_wait0();
        #pragma unroll
        for (int i = 0; i < 16; i++) {
            int kk = bk0 + 2 * i;
            float2 uf = __half22float2(*reinterpret_cast<const __half2*>(&nu[i]));
            float2 vf = __half22float2(*reinterpret_cast<const __half2*>(&nv[i]));
            float t0 = cw.x * uf.x + cw.y * vf.x;
            float t1 = cw.x * uf.y + cw.y * vf.y;
            BhS[sb + kk * BPIT128 + bj] = h16(cw.z * t0 + cw.w * t1);
        }
        __syncthreads();
        if (cc < c0 + 35) {
            const int nc = cc + 1;
            const int nn = nc >> 3;
            const int ci0 = (nc & 7) * 32;
            const int kg = nn * C1 + ci0;
            int g = bj * NS + nn;
            float4 w4 = gwS[g];
            int2 i2 = giS[g];
            const unsigned* plb = f2eb + ci0 * HPWP;
            #pragma unroll
            for (int i = 0; i < 16; i++) {
                int kk = bk0 + 2 * i;
                const unsigned* pl = plb + kk * HPWP;
                nu[i] = pl[i2.x];
                nv[i] = pl[i2.y];
            }
            cw = w4;
            const int na = (s ^ 1) * 64 * WPIT;
            cpa16(&AhS[na + far_ * WPIT + fac], g_w7h + far_ * KTOT + kg + fac);
            cpa16(&AlS[na + far_ * WPIT + fac], g_w7l + far_ * KTOT + kg + fac);
        }
        cpa_commit();
        #pragma unroll
        for (int ks = 0; ks < 2; ks++) {
            const int kb = ks * 16;
            unsigned ah[2][4];
            unsigned al[2][4];
            unsigned bh[4][2];
            #pragma unroll
            for (int mt = 0; mt < 2; mt++) {
                load_a_frag(ah[mt], AhS + sa, WPIT, m0 + mt * 16, kb, lane);
                load_a_frag(al[mt], AlS + sa, WPIT, m0 + mt * 16, kb, lane);
            }
            #pragma unroll
            for (int hf = 0; hf < 2; hf++) {
                load_b_frag(bh[hf * 2], bh[hf * 2 + 1], BhS + sb, BPIT128, kb, n0 + hf * 16, lane);
            }
            #pragma unroll
            for (int mt = 0; mt < 2; mt++) {
                #pragma unroll
                for (int nt = 0; nt < 4; nt++) {
                    mma16816(acc[mt][nt], ah[mt], bh[nt]);
                    mma16816(acc[mt][nt], al[mt], bh[nt]);
                }
            }
        }
    }
    #pragma unroll
    for (int mt = 0; mt < 2; mt++) {
        int o = m0 + mt * 16 + (lane >> 2);
        #pragma unroll
        for (int nt = 0; nt < 4; nt++) {
            int p = p0 + n0 + nt * 8 + 2 * (lane & 3);
            float2 v0;
            v0.x = acc[mt][nt][0];
            v0.y = acc[mt][nt][1];
            float2 v1;
            v1.x = acc[mt][nt][2];
            v1.y = acc[mt][nt][3];
            *(float2*)&dst[(bz * C2 + o) * HW + p] = v0;
            *(float2*)&dst[(bz * C2 + o + 8) * HW + p] = v1;
        }
    }
}

// ---------------- combine partials ----------------
__global__ void combine_kernel(float* __restrict__ out) {
    int i4 = blockIdx.x * blockDim.x + threadIdx.x;
    if (i4 >= OUTN / 4) {
        return;
    }
    float4 a = ((const float4*)g_do0)[i4];
    float4 b = ((const float4*)g_do1)[i4];
    float4 o;
    o.x = a.x + b.x;
    o.y = a.y + b.y;
    o.z = a.z + b.z;
    o.w = a.w + b.w;
    ((float4*)out)[i4] = o;
}

// ---------------- launch ----------------
extern "C" void kernel_launch(void* const* d_in, const int* in_sizes, int n_in,
                              void* d_out, int out_size) {
    const float* x = (const float*)d_in[0];
    const float* bn1_g = (const float*)d_in[1];
    const float* bn1_b = (const float*)d_in[2];
    const float* w1 = (const float*)d_in[3];
    const float* b1 = (const float*)d_in[4];
    const float* bn2_g = (const float*)d_in[5];
    const float* bn2_b = (const float*)d_in[6];
    const float* pw = (const float*)d_in[7];
    const float* pb = (const float*)d_in[8];
    const float* mw = (const float*)d_in[9];
    const float* mb = (const float*)d_in[10];
    const float* dw = (const float*)d_in[11];
    const float* db = (const float*)d_in[12];
    const float* w7 = (const float*)d_in[13];
    float* out = (float*)d_out;

    cudaFuncSetAttribute(conv1_kernel, cudaFuncAttributeMaxDynamicSharedMemorySize, C1_SMEM);
    cudaFuncSetAttribute(deform_kernel, cudaFuncAttributeMaxDynamicSharedMemorySize, DEF_SMEM);

    prep_kernel<<<(C2 * KTOT + 255) / 256, 256>>>(w1, pw, pb, mw, mb, dw, db, w7);
    bn1_partial_kernel<<<dim3(CIN, 4), 256>>>(x);
    xcvt_kernel<<<(BATCH * CIN * HW / 4 + 255) / 256, 256>>>(x, bn1_g, bn1_b);
    conv1_kernel<<<dim3(HW / 128, C1 / 128, BATCH), 256, C1_SMEM>>>(b1);
    bn2_partial_kernel<<<dim3(C1, 4), 256>>>();
    pad_bn2_kernel<<<(F2TOT + 255) / 256, 256>>>(bn2_g, bn2_b);
    offconv_kernel<<<dim3(HW / 128, 1, BATCH), 256>>>();
    deform_kernel<<<dim3(HW / 128, 2, BATCH), 256, DEF_SMEM>>>();
    combine_kernel<<<(OUTN / 4 + 255) / 256, 256>>>(out);
}